// round 7
// baseline (speedup 1.0000x reference)
#include <cuda_runtime.h>
#include <stdint.h>

// Depthwise 3x3 conv (256 ch x 2 filters) fused with butterfly wing-swap add.
//   out[c]  = conv(x[c],  w[2c])   + conv(x[cp], w[2cp+1])
//   out[cp] = conv(x[cp], w[2cp])  + conv(x[c],  w[2c+1]),  cp = c+4 within butterfly
// Register-streaming stencil: thread owns 2 cols x 28 rows of a channel pair,
// streams 30 input rows, 3 rolling packed accumulators (out_c, out_cp) per col.
// v=(x_c,x_cp)*W1=(w2c,w2cp) gives own-channel terms; vswap*(w2cp1,w2c1) cross terms.
// No data smem, no cp.async, no hot-loop syncs. Weights broadcast from smem.

#define CH 256
#define HW 56
#define PLANE (HW * HW)
#define NTHREADS 224     // 8 images x 28 strips
#define NBLOCKS 1024     // 128 pairs x 4 batch-groups x 2 row-halves

typedef unsigned long long ull;

__device__ __forceinline__ ull fma2(ull a, ull b, ull c) {
    ull d; asm("fma.rn.f32x2 %0, %1, %2, %3;" : "=l"(d) : "l"(a), "l"(b), "l"(c)); return d;
}
__device__ __forceinline__ ull pack2(float lo, float hi) {
    ull r; asm("mov.b64 %0, {%1, %2};" : "=l"(r) : "f"(lo), "f"(hi)); return r;
}
__device__ __forceinline__ float2 unpack2(ull v) {
    float2 r; asm("mov.b64 {%0, %1}, %2;" : "=f"(r.x), "=f"(r.y) : "l"(v)); return r;
}

__global__ __launch_bounds__(NTHREADS, 4)
void conv_butterfly_kernel(const float* __restrict__ x,
                           const float* __restrict__ w,
                           float* __restrict__ out)
{
    // weight rows t=0..2: [t*6+0..2] = W1[t][dc] = (w2c, w2cp)
    //                     [t*6+3..5] = W2[t][dc] = (w2cp+1, w2c+1)
    __shared__ __align__(16) ull wsm[18];

    const int tid  = threadIdx.x;
    const int b    = blockIdx.x;
    const int pair = b >> 3;
    const int sub  = b & 7;
    const int half = sub & 1;
    const int grp  = sub >> 1;                 // 0..3
    const int img  = tid / 28;                 // 0..7
    const int strip = tid - img * 28;          // 0..27
    const int n    = (grp << 3) + img;         // 0..31
    const int c    = ((pair >> 2) << 3) + (pair & 3);
    const int h0   = half * 28;
    const int c0   = strip << 1;

    if (tid < 18) {
        const float* wa = w + 18 * c;          // [w2c | w2c+1]
        const float* wb = w + 18 * (c + 4);    // [w2cp | w2cp+1]
        const int t = tid / 6, j = tid - t * 6;
        const int k = t * 3 + (j < 3 ? j : j - 3);
        wsm[tid] = (j < 3) ? pack2(__ldg(wa + k),     __ldg(wb + k))
                           : pack2(__ldg(wb + 9 + k), __ldg(wa + 9 + k));
    }
    __syncthreads();

    const float* px  = x + ((size_t)n * CH + c) * PLANE + c0;
    const float* pxr = px + h0 * HW;                       // row base (channel c)
    float* poc = out + ((size_t)n * CH + c) * PLANE + (size_t)h0 * HW + c0;
    float* pop = poc + 4 * PLANE;

    const bool hasL = (strip != 0);
    const bool hasR = (strip != 27);

    ull A[3][2];

#define APPLY(slot, t, FRESH) { \
    const ulonglong2 u0 = *(const ulonglong2*)(wsm + (t)*6 + 0); \
    const ulonglong2 u1 = *(const ulonglong2*)(wsm + (t)*6 + 2); \
    const ulonglong2 u2 = *(const ulonglong2*)(wsm + (t)*6 + 4); \
    ull a0 = (FRESH) ? 0ull : A[slot][0]; \
    ull a1 = (FRESH) ? 0ull : A[slot][1]; \
    a0 = fma2(v0, u0.x, a0); a0 = fma2(v1, u0.y, a0); a0 = fma2(v2, u1.x, a0); \
    a0 = fma2(s0, u1.y, a0); a0 = fma2(s1, u2.x, a0); a0 = fma2(s2, u2.y, a0); \
    a1 = fma2(v1, u0.x, a1); a1 = fma2(v2, u0.y, a1); a1 = fma2(v3, u1.x, a1); \
    a1 = fma2(s1, u1.y, a1); a1 = fma2(s2, u2.x, a1); a1 = fma2(s3, u2.y, a1); \
    A[slot][0] = a0; A[slot][1] = a1; }

    #pragma unroll
    for (int rl = -1; rl <= 28; ++rl) {        // input local row; global h0+rl
        ull v0, v1, v2, v3, s0, s1, s2, s3;
        const bool edge = (rl == -1) | (rl == 28);
        bool zero_row = false;
        if (edge) zero_row = (rl == -1) ? (h0 == 0) : (h0 == 28);
        if (zero_row) {
            v0 = v1 = v2 = v3 = 0ull;
            s0 = s1 = s2 = s3 = 0ull;
        } else {
            const float* rc = pxr + rl * HW;
            const float* rp = rc + 4 * PLANE;
            float l0 = 0.f, l1 = 0.f, r0 = 0.f, r1 = 0.f;
            if (hasL) { l0 = __ldg(rc - 1); l1 = __ldg(rp - 1); }
            const float2 m0 = __ldg((const float2*)rc);
            const float2 m1 = __ldg((const float2*)rp);
            if (hasR) { r0 = __ldg(rc + 2); r1 = __ldg(rp + 2); }
            v0 = pack2(l0,   l1);   s0 = pack2(l1,   l0);
            v1 = pack2(m0.x, m1.x); s1 = pack2(m1.x, m0.x);
            v2 = pack2(m0.y, m1.y); s2 = pack2(m1.y, m0.y);
            v3 = pack2(r0,   r1);   s3 = pack2(r1,   r0);
        }

        const int onew = rl + 1, omid = rl, oold = rl - 1;
        if (onew >= 0 && onew <= 27) APPLY(onew % 3, 0, true);
        if (omid >= 0 && omid <= 27) APPLY(omid % 3, 1, false);
        if (oold >= 0 && oold <= 27) {
            APPLY(oold % 3, 2, false);
            const int sl = oold % 3;
            const float2 a0 = unpack2(A[sl][0]);
            const float2 a1 = unpack2(A[sl][1]);
            *(float2*)(poc + oold * HW) = make_float2(a0.x, a1.x);
            *(float2*)(pop + oold * HW) = make_float2(a0.y, a1.y);
        }
    }
#undef APPLY
}

extern "C" void kernel_launch(void* const* d_in, const int* in_sizes, int n_in,
                              void* d_out, int out_size)
{
    const float* x = (const float*)d_in[0];
    const float* w = (const float*)d_in[1];
    float* out = (float*)d_out;
    (void)in_sizes; (void)n_in; (void)out_size;

    conv_butterfly_kernel<<<NBLOCKS, NTHREADS>>>(x, w, out);
}

// round 8
// speedup vs baseline: 1.2166x; 1.2166x over previous
#include <cuda_runtime.h>
#include <stdint.h>

// Depthwise 3x3 conv (256 ch x 2 filters) fused with butterfly wing-swap add.
//   out[c]  = conv(x[c],  w[2c])   + conv(x[cp], w[2cp+1])
//   out[cp] = conv(x[cp], w[2cp])  + conv(x[c],  w[2c+1]),  cp = c+4 within butterfly
// Persistent blocks, half-plane (28-row) tiles, double-buffered cp.async pipeline.
// Smem: channel-interleaved float2 (x_c, x_cp) -> LDS.64 feeds fma.rn.f32x2 directly.
// R8: 5 blocks/SM (reg cap 58 via launch_bounds) to lift occupancy 40% -> ~50%.

#define CH 256
#define HW 56
#define PLANE (HW * HW)
#define ST2 61                 // float2 elements per smem row (odd -> conflict-free)
#define TROWS 30               // 28 data rows + 2 halo slots
#define SPLANE2 (TROWS * ST2)  // 1830 float2 per buffer
#define NTHREADS 224           // 7 warps: 14 items/tile = exactly 2 per warp
#define NTILES 8192            // 32 batch * 128 pairs * 2 halves
#define GRID 760               // 5 blocks/SM * 152 SMs

typedef unsigned long long ull;

__device__ __forceinline__ ull fma2(ull a, ull b, ull c) {
    ull d; asm("fma.rn.f32x2 %0, %1, %2, %3;" : "=l"(d) : "l"(a), "l"(b), "l"(c)); return d;
}
__device__ __forceinline__ ull pack2(float lo, float hi) {
    ull r; asm("mov.b64 %0, {%1, %2};" : "=l"(r) : "f"(lo), "f"(hi)); return r;
}
__device__ __forceinline__ float2 unpack2(ull v) {
    float2 r; asm("mov.b64 {%0, %1}, %2;" : "=f"(r.x), "=f"(r.y) : "l"(v)); return r;
}

__global__ __launch_bounds__(NTHREADS, 5)
void conv_butterfly_kernel(const float* __restrict__ x,
                           const float* __restrict__ w,
                           float* __restrict__ out)
{
    extern __shared__ float2 sm[];               // [2 buffers][SPLANE2]
    __shared__ __align__(16) ull wsm[18];        // per-dr groups: Wc0,Wc1,Wc2,Wp0,Wp1,Wp2

    const int tid    = threadIdx.x;
    const int warpid = tid >> 5;                 // 0..6
    const int lane   = tid & 31;
    const int lr     = lane & 3;
    const int lc     = lane >> 2;
    const uint32_t smem0 = (uint32_t)__cvta_generic_to_shared(sm);

    // ---- zero pad columns (0 = left halo, 57..60 incl. right halo 57) once
    for (int i = tid; i < 2 * TROWS * 5; i += NTHREADS) {
        const int rs = i / 5;
        const int pc = i % 5;
        const int col = (pc == 0) ? 0 : (56 + pc);
        sm[rs * ST2 + col] = make_float2(0.f, 0.f);
    }

    // ---- prefetch half-tile t into buffer b (3360 4B copies, zfill OOB rows)
    auto prefetch = [&](int t, int b) {
        const int half = t & 1;
        const int p    = (t >> 1) & 127;
        const int n    = t >> 8;
        const int c    = ((p >> 2) << 3) + (p & 3);
        const int h0   = half * 28;
        const float* base = x + ((size_t)n * CH + c) * PLANE;
        #pragma unroll
        for (int k = 0; k < 15; k++) {
            const int i    = tid + k * NTHREADS;         // 0..3359
            const int slot = i / 112;                    // 0..29
            const int rem  = i - slot * 112;
            const int ch   = rem & 1;
            const int col  = rem >> 1;                   // 0..55
            const int h    = h0 - 1 + slot;              // -1..56
            const int sz   = (h >= 0 && h < HW) ? 4 : 0;
            const int hc   = min(max(h, 0), HW - 1);
            const float* src = base + ch * (4 * PLANE) + hc * HW + col;
            const uint32_t dst = smem0 +
                (uint32_t)(((b * SPLANE2 + slot * ST2 + 1 + col) << 3) + (ch << 2));
            asm volatile("cp.async.ca.shared.global [%0], [%1], 4, %2;"
                         :: "r"(dst), "l"(src), "r"(sz));
        }
    };

    int t = blockIdx.x;
    int b = 0;
    if (t < NTILES) prefetch(t, 0);
    asm volatile("cp.async.commit_group;");

    while (t < NTILES) {
        const int tn = t + GRID;
        if (tn < NTILES) prefetch(tn, b ^ 1);
        asm volatile("cp.async.commit_group;");

        const int half = t & 1;
        const int p    = (t >> 1) & 127;
        const int n    = t >> 8;
        const int c    = ((p >> 2) << 3) + (p & 3);
        const int h0   = half * 28;

        // stage packed weights in shared (18 threads, one ull each)
        if (tid < 18) {
            const float* wa = w + 18 * c;         // [w2c | w2c+1]
            const float* wb = w + 18 * (c + 4);   // [w2cp | w2cp+1]
            const int dr = tid / 6, sl = tid % 6;
            ull v;
            if (sl < 3) { const int k = dr * 3 + sl;     v = pack2(__ldg(wa + k),     __ldg(wb + 9 + k)); }
            else        { const int k = dr * 3 + sl - 3; v = pack2(__ldg(wa + 9 + k), __ldg(wb + k)); }
            wsm[tid] = v;
        }

        asm volatile("cp.async.wait_group 1;");
        __syncthreads();

        const ull* sbase = (const ull*)sm + b * SPLANE2;
        float* o0 = out + ((size_t)n * CH + c) * PLANE + h0 * HW;
        float* o1 = o0 + 4 * PLANE;

        const int rl = (warpid << 2) + lr;        // local output row 0..27

        #pragma unroll
        for (int pp = 0; pp < 2; pp++) {
            const int strip = (pp << 3) + lc;     // 0..15, active < 14
            if (strip < 14) {
                const int c0 = strip << 2;
                ull a0 = 0, a1 = 0, a2 = 0, a3 = 0;   // -> out[c]
                ull q0 = 0, q1 = 0, q2 = 0, q3 = 0;   // -> out[cp]
                #pragma unroll
                for (int dr = 0; dr < 3; dr++) {
                    const ull* qp = sbase + (rl + dr) * ST2 + c0;  // elements c0..c0+5
                    const ull v0 = qp[0], v1 = qp[1], v2 = qp[2];
                    const ull v3 = qp[3], v4 = qp[4], v5 = qp[5];
                    const ulonglong2 wA = *(const ulonglong2*)(wsm + dr * 6);
                    const ulonglong2 wB = *(const ulonglong2*)(wsm + dr * 6 + 2);
                    const ulonglong2 wC = *(const ulonglong2*)(wsm + dr * 6 + 4);
                    const ull wc0 = wA.x, wc1 = wA.y, wc2 = wB.x;
                    const ull wp0 = wB.y, wp1 = wC.x, wp2 = wC.y;

                    a0 = fma2(v0, wc0, a0); a0 = fma2(v1, wc1, a0); a0 = fma2(v2, wc2, a0);
                    a1 = fma2(v1, wc0, a1); a1 = fma2(v2, wc1, a1); a1 = fma2(v3, wc2, a1);
                    a2 = fma2(v2, wc0, a2); a2 = fma2(v3, wc1, a2); a2 = fma2(v4, wc2, a2);
                    a3 = fma2(v3, wc0, a3); a3 = fma2(v4, wc1, a3); a3 = fma2(v5, wc2, a3);

                    q0 = fma2(v0, wp0, q0); q0 = fma2(v1, wp1, q0); q0 = fma2(v2, wp2, q0);
                    q1 = fma2(v1, wp0, q1); q1 = fma2(v2, wp1, q1); q1 = fma2(v3, wp2, q1);
                    q2 = fma2(v2, wp0, q2); q2 = fma2(v3, wp1, q2); q2 = fma2(v4, wp2, q2);
                    q3 = fma2(v3, wp0, q3); q3 = fma2(v4, wp1, q3); q3 = fma2(v5, wp2, q3);
                }
                float2 u;
                float4 lo, hi;
                u = unpack2(a0); lo.x = u.x + u.y;
                u = unpack2(a1); lo.y = u.x + u.y;
                u = unpack2(a2); lo.z = u.x + u.y;
                u = unpack2(a3); lo.w = u.x + u.y;
                u = unpack2(q0); hi.x = u.x + u.y;
                u = unpack2(q1); hi.y = u.x + u.y;
                u = unpack2(q2); hi.z = u.x + u.y;
                u = unpack2(q3); hi.w = u.x + u.y;
                *(float4*)(o0 + rl * HW + c0) = lo;
                *(float4*)(o1 + rl * HW + c0) = hi;
            }
        }
        __syncthreads();      // protect buffer b and wsm before refill
        t = tn;
        b ^= 1;
    }
}

extern "C" void kernel_launch(void* const* d_in, const int* in_sizes, int n_in,
                              void* d_out, int out_size)
{
    const float* x = (const float*)d_in[0];
    const float* w = (const float*)d_in[1];
    float* out = (float*)d_out;
    (void)in_sizes; (void)n_in; (void)out_size;

    const int smem_bytes = 2 * SPLANE2 * (int)sizeof(float2);   // 29,280 B
    conv_butterfly_kernel<<<GRID, NTHREADS, smem_bytes>>>(x, w, out);
}